// round 1
// baseline (speedup 1.0000x reference)
#include <cuda_runtime.h>
#include <math.h>

// Problem shape (fixed by reference): q,k,v [2,16,2048,64] fp32
#define BB 2
#define HH 16
#define SS 2048
#define DD 64
#define BH (BB*HH)

#define TQ 16      // q rows per CTA
#define TKC 256    // k tile (phase 1)
#define NT 256     // threads per CTA

#define QT_STRIDE 20    // 16 + 4 pad (floats), keeps 16B alignment
#define KT_STRIDE 260   // 256 + 4 pad (floats), keeps 16B alignment
#define SMEM_FLOATS (TQ*SS + DD*QT_STRIDE + DD*KT_STRIDE)
#define SMEM_BYTES (SMEM_FLOATS * 4)   // 202752 B

// Normalized q (scaled by 1/T=10) and k, stored TRANSPOSED: [bh][d][s]
__device__ float g_qn[(size_t)BH * DD * SS];
__device__ float g_kn[(size_t)BH * DD * SS];

// ---------------------------------------------------------------------------
// Kernel 1: L2-normalize rows of q and k. One warp per row.
// Writes transposed layout [bh][d][s] so the attention kernel can stage
// k-tiles with coalesced loads and conflict-free smem stores.
// ---------------------------------------------------------------------------
__global__ void __launch_bounds__(256)
normalize_kernel(const float* __restrict__ q, const float* __restrict__ k) {
    const int warp = threadIdx.x >> 5;
    const int lane = threadIdx.x & 31;
    const long long id = (long long)blockIdx.x * 8 + warp; // 0 .. 2*BH*SS-1
    const long long nrows = (long long)BH * SS;
    const int is_k = (id >= nrows);
    const int row = (int)(is_k ? id - nrows : id);

    const float* src = is_k ? k : q;
    float* dst = is_k ? g_kn : g_qn;

    const float2 v2 = ((const float2*)(src + (size_t)row * DD))[lane];
    float ss = v2.x * v2.x + v2.y * v2.y;
    #pragma unroll
    for (int o = 16; o; o >>= 1) ss += __shfl_xor_sync(0xffffffffu, ss, o);

    float norm = sqrtf(ss);
    float scale = 1.0f / fmaxf(norm, 1e-12f);
    if (!is_k) scale *= 10.0f;  // fold 1/TEMPERATURE into q

    const int bh = row >> 11;   // row / SS
    const int s  = row & (SS - 1);
    float* base = dst + (size_t)bh * DD * SS + s;
    base[(size_t)(2 * lane) * SS]     = v2.x * scale;
    base[(size_t)(2 * lane + 1) * SS] = v2.y * scale;
}

// ---------------------------------------------------------------------------
// Kernel 2: per-CTA attention over 16 q rows of one (b,h).
//   Phase 1: logits[16][2048] = qn @ kn^T  (into smem)
//   Phase 2: rowwise softmax in smem, write score to gmem
//   Phase 3: out = P @ V
// ---------------------------------------------------------------------------
__global__ void __launch_bounds__(NT, 1)
attn_kernel(const float* __restrict__ v, float* __restrict__ outp,
            float* __restrict__ score) {
    extern __shared__ float smem[];
    float* logits = smem;                      // [TQ][SS]
    float* qt     = smem + TQ * SS;            // [DD][QT_STRIDE]
    float* kt     = qt + DD * QT_STRIDE;       // [DD][KT_STRIDE]

    const int t  = threadIdx.x;
    const int bh = blockIdx.x >> 7;            // 128 q-tiles per head
    const int q0 = (blockIdx.x & 127) * TQ;

    const float* qn = g_qn + (size_t)bh * DD * SS;
    const float* kn = g_kn + (size_t)bh * DD * SS;

    // ---- load q tile: qt[d][qi] = qn[d][q0+qi] ----
    {
        int d  = t >> 2;       // 0..63
        int qg = t & 3;        // 0..3 -> qi0 = qg*4
        float4 x = *(const float4*)(qn + (size_t)d * SS + q0 + qg * 4);
        *(float4*)(qt + d * QT_STRIDE + qg * 4) = x;
    }

    const int tq = t >> 6;     // 0..3  -> qi0 = tq*4
    const int tk = t & 63;     // 0..63 -> kj0 = tk*4

    // ================= Phase 1: logits =================
    for (int ksb = 0; ksb < SS; ksb += TKC) {
        __syncthreads();   // protect qt on first iter / kt reuse on later iters
        #pragma unroll
        for (int i = 0; i < 16; i++) {
            int fidx = i * NT + t;
            int d    = fidx >> 6;     // 0..63
            int kjg  = fidx & 63;     // 0..63 -> kj0 = kjg*4
            float4 x = *(const float4*)(kn + (size_t)d * SS + ksb + kjg * 4);
            *(float4*)(kt + d * KT_STRIDE + kjg * 4) = x;
        }
        __syncthreads();

        float acc[4][4];
        #pragma unroll
        for (int i = 0; i < 4; i++)
            #pragma unroll
            for (int j = 0; j < 4; j++) acc[i][j] = 0.0f;

        #pragma unroll 16
        for (int d = 0; d < DD; d++) {
            float4 a = *(const float4*)(qt + d * QT_STRIDE + tq * 4);
            float4 b = *(const float4*)(kt + d * KT_STRIDE + tk * 4);
            acc[0][0] += a.x * b.x; acc[0][1] += a.x * b.y;
            acc[0][2] += a.x * b.z; acc[0][3] += a.x * b.w;
            acc[1][0] += a.y * b.x; acc[1][1] += a.y * b.y;
            acc[1][2] += a.y * b.z; acc[1][3] += a.y * b.w;
            acc[2][0] += a.z * b.x; acc[2][1] += a.z * b.y;
            acc[2][2] += a.z * b.z; acc[2][3] += a.z * b.w;
            acc[3][0] += a.w * b.x; acc[3][1] += a.w * b.y;
            acc[3][2] += a.w * b.z; acc[3][3] += a.w * b.w;
        }

        #pragma unroll
        for (int i = 0; i < 4; i++) {
            float4 r = make_float4(acc[i][0], acc[i][1], acc[i][2], acc[i][3]);
            *(float4*)(logits + (size_t)(tq * 4 + i) * SS + ksb + tk * 4) = r;
        }
    }
    __syncthreads();

    // ================= Phase 2: softmax + score write =================
    {
        const int warp = t >> 5;
        const int lane = t & 31;
        for (int r = warp; r < TQ; r += 8) {
            float* row = logits + (size_t)r * SS;
            float m = -3.0e38f;
            for (int c = lane * 4; c < SS; c += 128) {
                float4 x = *(const float4*)(row + c);
                m = fmaxf(m, fmaxf(fmaxf(x.x, x.y), fmaxf(x.z, x.w)));
            }
            #pragma unroll
            for (int o = 16; o; o >>= 1) m = fmaxf(m, __shfl_xor_sync(0xffffffffu, m, o));

            float sum = 0.0f;
            for (int c = lane * 4; c < SS; c += 128) {
                float4 x = *(const float4*)(row + c);
                x.x = __expf(x.x - m);
                x.y = __expf(x.y - m);
                x.z = __expf(x.z - m);
                x.w = __expf(x.w - m);
                sum += x.x + x.y + x.z + x.w;
                *(float4*)(row + c) = x;
            }
            #pragma unroll
            for (int o = 16; o; o >>= 1) sum += __shfl_xor_sync(0xffffffffu, sum, o);

            float inv = 1.0f / sum;
            float* grow = score + ((size_t)bh * SS + q0 + r) * SS;
            for (int c = lane * 4; c < SS; c += 128) {
                float4 x = *(const float4*)(row + c);
                x.x *= inv; x.y *= inv; x.z *= inv; x.w *= inv;
                *(float4*)(row + c) = x;       // keep P in smem for phase 3
                *(float4*)(grow + c) = x;      // materialize score
            }
        }
    }
    __syncthreads();

    // ================= Phase 3: out = P @ V =================
    {
        float* vs  = kt;              // [64][64], overlays kt
        float* red = kt + 4096;       // [4][64][16]

        const int pos   = t & 63;
        const int slice = t >> 6;     // k-slice 0..3
        const int qg    = pos >> 4;   // 0..3 -> qi0 = qg*4
        const int dg    = pos & 15;   // 0..15 -> d0 = dg*4

        float4 a0 = make_float4(0, 0, 0, 0);
        float4 a1 = a0, a2 = a0, a3 = a0;
        const float* vb = v + (size_t)bh * SS * DD;

        for (int ksb = 0; ksb < SS; ksb += 64) {
            __syncthreads();   // previous tile's compute done before vs overwrite
            #pragma unroll
            for (int i = 0; i < 4; i++) {
                int fidx = i * NT + t;
                int kk = fidx >> 4;   // 0..63
                int c  = fidx & 15;   // 0..15
                float4 x = *(const float4*)(vb + (size_t)(ksb + kk) * DD + c * 4);
                *(float4*)(vs + kk * DD + c * 4) = x;
            }
            __syncthreads();

            #pragma unroll 16
            for (int k2 = 0; k2 < 16; k2++) {
                int kk = slice * 16 + k2;
                float4 vv = *(const float4*)(vs + kk * DD + dg * 4);
                float p0 = logits[(size_t)(qg * 4 + 0) * SS + ksb + kk];
                float p1 = logits[(size_t)(qg * 4 + 1) * SS + ksb + kk];
                float p2 = logits[(size_t)(qg * 4 + 2) * SS + ksb + kk];
                float p3 = logits[(size_t)(qg * 4 + 3) * SS + ksb + kk];
                a0.x += p0 * vv.x; a0.y += p0 * vv.y; a0.z += p0 * vv.z; a0.w += p0 * vv.w;
                a1.x += p1 * vv.x; a1.y += p1 * vv.y; a1.z += p1 * vv.z; a1.w += p1 * vv.w;
                a2.x += p2 * vv.x; a2.y += p2 * vv.y; a2.z += p2 * vv.z; a2.w += p2 * vv.w;
                a3.x += p3 * vv.x; a3.y += p3 * vv.y; a3.z += p3 * vv.z; a3.w += p3 * vv.w;
            }
        }
        __syncthreads();

        float* m = red + (size_t)(slice * 64 + pos) * 16;
        *(float4*)(m + 0)  = a0;
        *(float4*)(m + 4)  = a1;
        *(float4*)(m + 8)  = a2;
        *(float4*)(m + 12) = a3;
        __syncthreads();

        float* ob = outp + (size_t)bh * SS * DD + (size_t)q0 * DD;
        for (int e = t; e < TQ * DD; e += NT) {
            int qi = e >> 6;          // 0..15
            int d  = e & 63;          // 0..63
            int p2 = (qi >> 2) * 16 + (d >> 2);
            int sl = (qi & 3) * 4 + (d & 3);
            float sum = 0.0f;
            #pragma unroll
            for (int s2 = 0; s2 < 4; s2++)
                sum += red[(size_t)(s2 * 64 + p2) * 16 + sl];
            ob[e] = sum;
        }
    }
}

// ---------------------------------------------------------------------------
extern "C" void kernel_launch(void* const* d_in, const int* in_sizes, int n_in,
                              void* d_out, int out_size) {
    const float* q = (const float*)d_in[0];
    const float* k = (const float*)d_in[1];
    const float* v = (const float*)d_in[2];

    float* outp  = (float*)d_out;                          // [B,H,S,D]
    float* score = outp + (size_t)BH * SS * DD;            // [B,H,S,S] follows

    cudaFuncSetAttribute(attn_kernel,
                         cudaFuncAttributeMaxDynamicSharedMemorySize, SMEM_BYTES);

    // 2 * BH * SS rows total, 8 warps (rows) per block
    normalize_kernel<<<(2 * BH * SS) / 8, 256>>>(q, k);
    attn_kernel<<<BH * (SS / TQ), NT, SMEM_BYTES>>>(v, outp, score);
}

// round 2
// speedup vs baseline: 1.0497x; 1.0497x over previous
#include <cuda_runtime.h>
#include <math.h>

// Problem shape (fixed by reference): q,k,v [2,16,2048,64] fp32
#define BB 2
#define HH 16
#define SS 2048
#define DD 64
#define BH (BB*HH)

#define TQ 16      // q rows per CTA
#define TKC 256    // k tile (phase 1)
#define NT 256     // threads per CTA

#define QT_STRIDE 20    // 16 + 4 pad (floats), keeps 16B alignment
#define KT_STRIDE 260   // 256 + 4 pad (floats), keeps 16B alignment
#define SMEM_FLOATS (TQ*SS + DD*QT_STRIDE + DD*KT_STRIDE)
#define SMEM_BYTES (SMEM_FLOATS * 4)   // 202752 B

// Normalized q (scaled by 1/T=10) and k, stored TRANSPOSED: [bh][d][s]
__device__ float g_qn[(size_t)BH * DD * SS];
__device__ float g_kn[(size_t)BH * DD * SS];

// ---------------------------------------------------------------------------
// Kernel 1: L2-normalize rows of q and k. One warp per row.
// Writes transposed layout [bh][d][s] so the attention kernel can stage
// k-tiles with coalesced loads and conflict-free smem stores.
// ---------------------------------------------------------------------------
__global__ void __launch_bounds__(256)
normalize_kernel(const float* __restrict__ q, const float* __restrict__ k) {
    const int warp = threadIdx.x >> 5;
    const int lane = threadIdx.x & 31;
    const long long id = (long long)blockIdx.x * 8 + warp; // 0 .. 2*BH*SS-1
    const long long nrows = (long long)BH * SS;
    const int is_k = (id >= nrows);
    const int row = (int)(is_k ? id - nrows : id);

    const float* src = is_k ? k : q;
    float* dst = is_k ? g_kn : g_qn;

    const float2 v2 = ((const float2*)(src + (size_t)row * DD))[lane];
    float ss = v2.x * v2.x + v2.y * v2.y;
    #pragma unroll
    for (int o = 16; o; o >>= 1) ss += __shfl_xor_sync(0xffffffffu, ss, o);

    float norm = sqrtf(ss);
    float scale = 1.0f / fmaxf(norm, 1e-12f);
    if (!is_k) scale *= 10.0f;  // fold 1/TEMPERATURE into q

    const int bh = row >> 11;   // row / SS
    const int s  = row & (SS - 1);
    float* base = dst + (size_t)bh * DD * SS + s;
    base[(size_t)(2 * lane) * SS]     = v2.x * scale;
    base[(size_t)(2 * lane + 1) * SS] = v2.y * scale;
}

// ---------------------------------------------------------------------------
// Kernel 2: per-CTA attention over 16 q rows of one (b,h).
//   Phase 1: logits[16][2048] = qn @ kn^T  (into smem)
//   Phase 2: rowwise softmax in smem, write score to gmem
//   Phase 3: out = P @ V
// ---------------------------------------------------------------------------
__global__ void __launch_bounds__(NT, 1)
attn_kernel(const float* __restrict__ v, float* __restrict__ outp,
            float* __restrict__ score) {
    extern __shared__ float smem[];
    float* logits = smem;                      // [TQ][SS]
    float* qt     = smem + TQ * SS;            // [DD][QT_STRIDE]
    float* kt     = qt + DD * QT_STRIDE;       // [DD][KT_STRIDE]

    const int t  = threadIdx.x;
    const int bh = blockIdx.x >> 7;            // 128 q-tiles per head
    const int q0 = (blockIdx.x & 127) * TQ;

    const float* qn = g_qn + (size_t)bh * DD * SS;
    const float* kn = g_kn + (size_t)bh * DD * SS;

    // ---- load q tile: qt[d][qi] = qn[d][q0+qi] ----
    {
        int d  = t >> 2;       // 0..63
        int qg = t & 3;        // 0..3 -> qi0 = qg*4
        float4 x = *(const float4*)(qn + (size_t)d * SS + q0 + qg * 4);
        *(float4*)(qt + d * QT_STRIDE + qg * 4) = x;
    }

    const int tq = t >> 6;     // 0..3  -> qi0 = tq*4
    const int tk = t & 63;     // 0..63 -> kj0 = tk*4

    // ================= Phase 1: logits =================
    for (int ksb = 0; ksb < SS; ksb += TKC) {
        __syncthreads();   // protect qt on first iter / kt reuse on later iters
        #pragma unroll
        for (int i = 0; i < 16; i++) {
            int fidx = i * NT + t;
            int d    = fidx >> 6;     // 0..63
            int kjg  = fidx & 63;     // 0..63 -> kj0 = kjg*4
            float4 x = *(const float4*)(kn + (size_t)d * SS + ksb + kjg * 4);
            *(float4*)(kt + d * KT_STRIDE + kjg * 4) = x;
        }
        __syncthreads();

        float acc[4][4];
        #pragma unroll
        for (int i = 0; i < 4; i++)
            #pragma unroll
            for (int j = 0; j < 4; j++) acc[i][j] = 0.0f;

        #pragma unroll 16
        for (int d = 0; d < DD; d++) {
            float4 a = *(const float4*)(qt + d * QT_STRIDE + tq * 4);
            float4 b = *(const float4*)(kt + d * KT_STRIDE + tk * 4);
            acc[0][0] += a.x * b.x; acc[0][1] += a.x * b.y;
            acc[0][2] += a.x * b.z; acc[0][3] += a.x * b.w;
            acc[1][0] += a.y * b.x; acc[1][1] += a.y * b.y;
            acc[1][2] += a.y * b.z; acc[1][3] += a.y * b.w;
            acc[2][0] += a.z * b.x; acc[2][1] += a.z * b.y;
            acc[2][2] += a.z * b.z; acc[2][3] += a.z * b.w;
            acc[3][0] += a.w * b.x; acc[3][1] += a.w * b.y;
            acc[3][2] += a.w * b.z; acc[3][3] += a.w * b.w;
        }

        #pragma unroll
        for (int i = 0; i < 4; i++) {
            float4 r = make_float4(acc[i][0], acc[i][1], acc[i][2], acc[i][3]);
            *(float4*)(logits + (size_t)(tq * 4 + i) * SS + ksb + tk * 4) = r;
        }
    }
    __syncthreads();

    // ================= Phase 2: softmax + score write =================
    {
        const int warp = t >> 5;
        const int lane = t & 31;
        for (int r = warp; r < TQ; r += 8) {
            float* row = logits + (size_t)r * SS;
            float m = -3.0e38f;
            for (int c = lane * 4; c < SS; c += 128) {
                float4 x = *(const float4*)(row + c);
                m = fmaxf(m, fmaxf(fmaxf(x.x, x.y), fmaxf(x.z, x.w)));
            }
            #pragma unroll
            for (int o = 16; o; o >>= 1) m = fmaxf(m, __shfl_xor_sync(0xffffffffu, m, o));

            float sum = 0.0f;
            for (int c = lane * 4; c < SS; c += 128) {
                float4 x = *(const float4*)(row + c);
                x.x = __expf(x.x - m);
                x.y = __expf(x.y - m);
                x.z = __expf(x.z - m);
                x.w = __expf(x.w - m);
                sum += x.x + x.y + x.z + x.w;
                *(float4*)(row + c) = x;
            }
            #pragma unroll
            for (int o = 16; o; o >>= 1) sum += __shfl_xor_sync(0xffffffffu, sum, o);

            float inv = 1.0f / sum;
            float* grow = score + ((size_t)bh * SS + q0 + r) * SS;
            for (int c = lane * 4; c < SS; c += 128) {
                float4 x = *(const float4*)(row + c);
                x.x *= inv; x.y *= inv; x.z *= inv; x.w *= inv;
                *(float4*)(row + c) = x;       // keep P in smem for phase 3
                *(float4*)(grow + c) = x;      // materialize score
            }
        }
    }
    __syncthreads();

    // ================= Phase 3: out = P @ V =================
    {
        float* vs  = kt;              // [64][64], overlays kt
        float* red = kt + 4096;       // [4][64][16]

        const int pos   = t & 63;
        const int slice = t >> 6;     // k-slice 0..3
        const int qg    = pos >> 4;   // 0..3 -> qi0 = qg*4
        const int dg    = pos & 15;   // 0..15 -> d0 = dg*4

        float4 a0 = make_float4(0, 0, 0, 0);
        float4 a1 = a0, a2 = a0, a3 = a0;
        const float* vb = v + (size_t)bh * SS * DD;

        for (int ksb = 0; ksb < SS; ksb += 64) {
            __syncthreads();   // previous tile's compute done before vs overwrite
            #pragma unroll
            for (int i = 0; i < 4; i++) {
                int fidx = i * NT + t;
                int kk = fidx >> 4;   // 0..63
                int c  = fidx & 15;   // 0..15
                float4 x = *(const float4*)(vb + (size_t)(ksb + kk) * DD + c * 4);
                *(float4*)(vs + kk * DD + c * 4) = x;
            }
            __syncthreads();

            #pragma unroll 16
            for (int k2 = 0; k2 < 16; k2++) {
                int kk = slice * 16 + k2;
                float4 vv = *(const float4*)(vs + kk * DD + dg * 4);
                float p0 = logits[(size_t)(qg * 4 + 0) * SS + ksb + kk];
                float p1 = logits[(size_t)(qg * 4 + 1) * SS + ksb + kk];
                float p2 = logits[(size_t)(qg * 4 + 2) * SS + ksb + kk];
                float p3 = logits[(size_t)(qg * 4 + 3) * SS + ksb + kk];
                a0.x += p0 * vv.x; a0.y += p0 * vv.y; a0.z += p0 * vv.z; a0.w += p0 * vv.w;
                a1.x += p1 * vv.x; a1.y += p1 * vv.y; a1.z += p1 * vv.z; a1.w += p1 * vv.w;
                a2.x += p2 * vv.x; a2.y += p2 * vv.y; a2.z += p2 * vv.z; a2.w += p2 * vv.w;
                a3.x += p3 * vv.x; a3.y += p3 * vv.y; a3.z += p3 * vv.z; a3.w += p3 * vv.w;
            }
        }
        __syncthreads();

        float* m = red + (size_t)(slice * 64 + pos) * 16;
        *(float4*)(m + 0)  = a0;
        *(float4*)(m + 4)  = a1;
        *(float4*)(m + 8)  = a2;
        *(float4*)(m + 12) = a3;
        __syncthreads();

        float* ob = outp + (size_t)bh * SS * DD + (size_t)q0 * DD;
        for (int e = t; e < TQ * DD; e += NT) {
            int qi = e >> 6;          // 0..15
            int d  = e & 63;          // 0..63
            int p2 = (qi >> 2) * 16 + (d >> 2);
            int sl = (qi & 3) * 4 + (d & 3);
            float sum = 0.0f;
            #pragma unroll
            for (int s2 = 0; s2 < 4; s2++)
                sum += red[(size_t)(s2 * 64 + p2) * 16 + sl];
            ob[e] = sum;
        }
    }
}

// ---------------------------------------------------------------------------
extern "C" void kernel_launch(void* const* d_in, const int* in_sizes, int n_in,
                              void* d_out, int out_size) {
    const float* q = (const float*)d_in[0];
    const float* k = (const float*)d_in[1];
    const float* v = (const float*)d_in[2];

    float* outp  = (float*)d_out;                          // [B,H,S,D]
    float* score = outp + (size_t)BH * SS * DD;            // [B,H,S,S] follows

    cudaFuncSetAttribute(attn_kernel,
                         cudaFuncAttributeMaxDynamicSharedMemorySize, SMEM_BYTES);

    // 2 * BH * SS rows total, 8 warps (rows) per block
    normalize_kernel<<<(2 * BH * SS) / 8, 256>>>(q, k);
    attn_kernel<<<BH * (SS / TQ), NT, SMEM_BYTES>>>(v, outp, score);
}

// round 3
// speedup vs baseline: 1.2809x; 1.2203x over previous
#include <cuda_runtime.h>
#include <math.h>

// Problem shape: q,k,v [2,16,2048,64] fp32
#define BB 2
#define HH 16
#define SS 2048
#define DD 64
#define BH (BB*HH)

#define NT 256          // threads per CTA
#define TQ 16           // q rows per CTA

#define LSTRIDE 2052    // logits row stride (2048 + 4): stride%32 == 4 -> conflict-free frag loads
#define QTS 68          // q tile stride (64+4)
#define KTS 264         // k tile stride (256+8): stride%32 == 8
#define VTS 72          // v tile stride (64+8):  stride%32 == 8

#define SCRATCH_FLOATS (256*VTS)   // 18432: max(kt 64*264=16896, vs 256*72=18432, red 8*1024=8192)
#define SMEM_FLOATS (TQ*LSTRIDE + TQ*QTS + SCRATCH_FLOATS)
#define SMEM_BYTES (SMEM_FLOATS*4)  // 209408

// tf32-rounded operands.
// g_qn: normalized q * 10, row-major [bh][s][d]
// g_kn: normalized k, transposed [bh][d][s]
// g_vr: v rounded, row-major [bh][s][d]
__device__ unsigned g_qn[(size_t)BH * SS * DD];
__device__ unsigned g_kn[(size_t)BH * DD * SS];
__device__ unsigned g_vr[(size_t)BH * SS * DD];

__device__ __forceinline__ unsigned tf32r(float f) {
    unsigned u;
    asm("cvt.rna.tf32.f32 %0, %1;" : "=r"(u) : "f"(f));
    return u;
}

__device__ __forceinline__ void mma_tf32(float& d0, float& d1, float& d2, float& d3,
                                         unsigned a0, unsigned a1, unsigned a2, unsigned a3,
                                         unsigned b0, unsigned b1) {
    asm volatile(
        "mma.sync.aligned.m16n8k8.row.col.f32.tf32.tf32.f32 "
        "{%0,%1,%2,%3}, {%4,%5,%6,%7}, {%8,%9}, {%0,%1,%2,%3};"
        : "+f"(d0), "+f"(d1), "+f"(d2), "+f"(d3)
        : "r"(a0), "r"(a1), "r"(a2), "r"(a3), "r"(b0), "r"(b1));
}

// ---------------------------------------------------------------------------
// Prep: L2-normalize q (x10) and k, round all operands (incl. v) to tf32.
// One warp per 64-elem row.
// ---------------------------------------------------------------------------
__global__ void __launch_bounds__(256)
prep_kernel(const float* __restrict__ q, const float* __restrict__ k,
            const float* __restrict__ v) {
    const int warp = threadIdx.x >> 5;
    const int lane = threadIdx.x & 31;
    const long long id = (long long)blockIdx.x * 8 + warp;
    const long long nrows = (long long)BH * SS;           // 65536
    const int seg = (int)(id / nrows);                    // 0=q, 1=k, 2=v
    const int row = (int)(id - (long long)seg * nrows);

    const float* src = (seg == 0) ? q : (seg == 1 ? k : v);
    const float2 v2 = ((const float2*)(src + (size_t)row * DD))[lane];

    if (seg == 2) {
        ((uint2*)(g_vr + (size_t)row * DD))[lane] = make_uint2(tf32r(v2.x), tf32r(v2.y));
        return;
    }

    float ss = v2.x * v2.x + v2.y * v2.y;
    #pragma unroll
    for (int o = 16; o; o >>= 1) ss += __shfl_xor_sync(0xffffffffu, ss, o);
    float scale = 1.0f / fmaxf(sqrtf(ss), 1e-12f);
    if (seg == 0) scale *= 10.0f;  // fold 1/TEMPERATURE into q

    if (seg == 0) {
        ((uint2*)(g_qn + (size_t)row * DD))[lane] =
            make_uint2(tf32r(v2.x * scale), tf32r(v2.y * scale));
    } else {
        const int bh = row >> 11;
        const int s  = row & (SS - 1);
        unsigned* base = g_kn + (size_t)bh * DD * SS + s;
        base[(size_t)(2 * lane) * SS]     = tf32r(v2.x * scale);
        base[(size_t)(2 * lane + 1) * SS] = tf32r(v2.y * scale);
    }
}

// ---------------------------------------------------------------------------
// Attention: one CTA = 16 q rows of one (b,h). Tensor-core tf32 GEMMs.
// ---------------------------------------------------------------------------
__global__ void __launch_bounds__(NT, 1)
attn_kernel(float* __restrict__ outp, float* __restrict__ score) {
    extern __shared__ float smem[];
    float* logits  = smem;                         // [16][LSTRIDE]
    float* qt      = smem + TQ * LSTRIDE;          // [16][QTS]  (sums after phase 1)
    float* scratch = qt + TQ * QTS;                // kt / vs / red

    const int t    = threadIdx.x;
    const int lane = t & 31;
    const int warp = t >> 5;
    const int gp   = lane >> 2;   // group (0..7)
    const int tid4 = lane & 3;    // thread in group

    const int bh = blockIdx.x >> 7;
    const int q0 = (blockIdx.x & 127) * TQ;

    const unsigned* qn = g_qn + (size_t)bh * SS * DD;  // [s][d]
    const unsigned* kn = g_kn + (size_t)bh * DD * SS;  // [d][s]
    const unsigned* vr = g_vr + (size_t)bh * SS * DD;  // [s][d]

    // ---- stage q tile (already tf32-rounded) ----
    {
        int qi = t >> 4, d4 = t & 15;
        uint4 x = *(const uint4*)(qn + (size_t)(q0 + qi) * DD + d4 * 4);
        *(uint4*)((unsigned*)qt + qi * QTS + d4 * 4) = x;
    }
    __syncthreads();

    // ---- A fragments for phase 1: entire 16x64 Q tile in registers ----
    unsigned a[8][4];
    {
        const unsigned* qtu = (const unsigned*)qt;
        #pragma unroll
        for (int ks = 0; ks < 8; ks++) {
            a[ks][0] = qtu[gp * QTS + ks * 8 + tid4];
            a[ks][1] = qtu[(gp + 8) * QTS + ks * 8 + tid4];
            a[ks][2] = qtu[gp * QTS + ks * 8 + tid4 + 4];
            a[ks][3] = qtu[(gp + 8) * QTS + ks * 8 + tid4 + 4];
        }
    }

    // ================= Phase 1: logits = Qn @ Kn^T =================
    {
        float* kt = scratch;                       // [64][KTS]
        const unsigned* ktu = (const unsigned*)kt;
        for (int ksb = 0; ksb < SS; ksb += 256) {
            __syncthreads();
            #pragma unroll
            for (int i = 0; i < 16; i++) {
                int fidx = i * NT + t;
                int d = fidx >> 6, c4 = fidx & 63;
                uint4 x = *(const uint4*)(kn + (size_t)d * SS + ksb + c4 * 4);
                *(uint4*)((unsigned*)kt + d * KTS + c4 * 4) = x;
            }
            __syncthreads();

            #pragma unroll
            for (int nt2 = 0; nt2 < 4; nt2++) {
                int n0 = warp * 32 + nt2 * 8;
                float d0 = 0.f, d1 = 0.f, d2 = 0.f, d3 = 0.f;
                #pragma unroll
                for (int ks = 0; ks < 8; ks++) {
                    unsigned b0 = ktu[(ks * 8 + tid4) * KTS + n0 + gp];
                    unsigned b1 = ktu[(ks * 8 + 4 + tid4) * KTS + n0 + gp];
                    mma_tf32(d0, d1, d2, d3, a[ks][0], a[ks][1], a[ks][2], a[ks][3], b0, b1);
                }
                float* lg = logits + gp * LSTRIDE + ksb + n0 + tid4 * 2;
                *(float2*)lg = make_float2(d0, d1);
                *(float2*)(lg + 8 * LSTRIDE) = make_float2(d2, d3);
            }
        }
    }
    __syncthreads();

    // ================= Phase 2: exp + sums + score write =================
    // logits in [-10,10] strictly -> exp never overflows; softmax is
    // shift-invariant so skipping max subtraction gives identical results.
    float* sums = qt;   // 16 floats, qt region is dead now
    for (int r = warp; r < TQ; r += 8) {
        float* row = logits + (size_t)r * LSTRIDE;
        float s = 0.0f;
        for (int c = lane * 4; c < SS; c += 128) {
            float4 x = *(const float4*)(row + c);
            x.x = __expf(x.x); x.y = __expf(x.y);
            x.z = __expf(x.z); x.w = __expf(x.w);
            s += x.x + x.y + x.z + x.w;
            *(float4*)(row + c) = x;   // keep unnormalized exp for phase 3
        }
        #pragma unroll
        for (int o = 16; o; o >>= 1) s += __shfl_xor_sync(0xffffffffu, s, o);
        if (lane == 0) sums[r] = 1.0f / s;
    }
    // same warp that produced sums[r] consumes it for the score write
    for (int r = warp; r < TQ; r += 8) {
        float inv = sums[r];
        float* row  = logits + (size_t)r * LSTRIDE;
        float* grow = score + ((size_t)bh * SS + q0 + r) * SS;
        for (int c = lane * 4; c < SS; c += 128) {
            float4 x = *(const float4*)(row + c);
            x.x *= inv; x.y *= inv; x.z *= inv; x.w *= inv;
            *(float4*)(grow + c) = x;
        }
    }

    // ================= Phase 3: out = exp(L) @ V, scaled by inv_sum =========
    // Warp w owns k-slice [w*32, w*32+32) of each 256-chunk, full N=64.
    float acc[8][4];
    #pragma unroll
    for (int i = 0; i < 8; i++)
        #pragma unroll
        for (int j = 0; j < 4; j++) acc[i][j] = 0.0f;

    {
        float* vs = scratch;                      // [256][VTS]
        const unsigned* vsu = (const unsigned*)vs;
        for (int c = 0; c < 8; c++) {
            __syncthreads();   // prev chunk consumed (and, first iter, phase-2 done)
            #pragma unroll
            for (int i = 0; i < 16; i++) {
                int fidx = i * NT + t;
                int kk = fidx >> 4, d4 = fidx & 15;
                uint4 x = *(const uint4*)(vr + (size_t)(c * 256 + kk) * DD + d4 * 4);
                *(uint4*)((unsigned*)vs + kk * VTS + d4 * 4) = x;
            }
            __syncthreads();

            #pragma unroll
            for (int ks = 0; ks < 4; ks++) {
                int kl  = warp * 32 + ks * 8;      // k offset within chunk
                int kgl = c * 256 + kl;            // global k (logits col)
                unsigned a0 = tf32r(logits[gp * LSTRIDE + kgl + tid4]);
                unsigned a1 = tf32r(logits[(gp + 8) * LSTRIDE + kgl + tid4]);
                unsigned a2 = tf32r(logits[gp * LSTRIDE + kgl + tid4 + 4]);
                unsigned a3 = tf32r(logits[(gp + 8) * LSTRIDE + kgl + tid4 + 4]);
                #pragma unroll
                for (int nt2 = 0; nt2 < 8; nt2++) {
                    unsigned b0 = vsu[(kl + tid4) * VTS + nt2 * 8 + gp];
                    unsigned b1 = vsu[(kl + tid4 + 4) * VTS + nt2 * 8 + gp];
                    mma_tf32(acc[nt2][0], acc[nt2][1], acc[nt2][2], acc[nt2][3],
                             a0, a1, a2, a3, b0, b1);
                }
            }
        }
    }
    __syncthreads();

    // cross-warp reduction of partial sums
    float* red = scratch;   // [8][16*64]
    #pragma unroll
    for (int nt2 = 0; nt2 < 8; nt2++) {
        float* m = red + warp * (TQ * DD) + gp * DD + nt2 * 8 + tid4 * 2;
        *(float2*)m = make_float2(acc[nt2][0], acc[nt2][1]);
        *(float2*)(m + 8 * DD) = make_float2(acc[nt2][2], acc[nt2][3]);
    }
    __syncthreads();

    {
        float* ob = outp + ((size_t)bh * SS + q0) * DD;
        int qi = t >> 4, d0 = (t & 15) * 4;
        float4 s4 = make_float4(0, 0, 0, 0);
        #pragma unroll
        for (int w = 0; w < 8; w++) {
            float4 x = *(const float4*)(red + w * (TQ * DD) + qi * DD + d0);
            s4.x += x.x; s4.y += x.y; s4.z += x.z; s4.w += x.w;
        }
        float inv = sums[qi];
        s4.x *= inv; s4.y *= inv; s4.z *= inv; s4.w *= inv;
        *(float4*)(ob + qi * DD + d0) = s4;
    }
}

// ---------------------------------------------------------------------------
extern "C" void kernel_launch(void* const* d_in, const int* in_sizes, int n_in,
                              void* d_out, int out_size) {
    const float* q = (const float*)d_in[0];
    const float* k = (const float*)d_in[1];
    const float* v = (const float*)d_in[2];

    float* outp  = (float*)d_out;                 // [B,H,S,D]
    float* score = outp + (size_t)BH * SS * DD;   // [B,H,S,S]

    cudaFuncSetAttribute(attn_kernel,
                         cudaFuncAttributeMaxDynamicSharedMemorySize, SMEM_BYTES);

    prep_kernel<<<(3 * BH * SS) / 8, 256>>>(q, k, v);
    attn_kernel<<<BH * (SS / TQ), NT, SMEM_BYTES>>>(outp, score);
}

// round 6
// speedup vs baseline: 2.1493x; 1.6780x over previous
#include <cuda_runtime.h>
#include <cstdint>
#include <math.h>

// Problem shape: q,k,v [2,16,2048,64] fp32
#define BB 2
#define HH 16
#define SS 2048
#define DD 64
#define BH (BB*HH)

#define NT 256          // threads per CTA
#define TQ 16           // q rows per CTA

#define LSTRIDE 2052    // logits row stride (2048+4): %32==4 -> conflict-free frag loads
#define QTS 68          // q tile stride (64+4)
#define KTS 264         // k tile stride (256+8): %32==8
#define VTS 72          // v tile stride (64+8):  %32==8

#define OFF_LOG 0
#define OFF_QT  (TQ*LSTRIDE)            // 32832  (sums[16] + part[128] live here later)
#define OFF_SCR (OFF_QT + TQ*QTS)       // 33920  (kt 16896 | vs 2x9216)
#define SMEM_F  (OFF_SCR + 18432)       // 52352
#define SMEM_BYTES (SMEM_F*4)           // 209408

// tf32-rounded operands.
__device__ unsigned g_qn[(size_t)BH * SS * DD];   // normalized q*10, [bh][s][d]
__device__ unsigned g_kn[(size_t)BH * DD * SS];   // normalized k, transposed [bh][d][s]
__device__ unsigned g_vr[(size_t)BH * SS * DD];   // v rounded, [bh][s][d]

static __device__ __forceinline__ unsigned tf32r(float f) {
    unsigned u; asm("cvt.rna.tf32.f32 %0, %1;" : "=r"(u) : "f"(f)); return u;
}
static __device__ __forceinline__ uint32_t s2u(const void* p) {
    uint32_t a;
    asm("{ .reg .u64 t; cvta.to.shared.u64 t, %1; cvt.u32.u64 %0, t; }" : "=r"(a) : "l"(p));
    return a;
}
static __device__ __forceinline__ void cpa16(uint32_t dst, const void* src) {
    asm volatile("cp.async.cg.shared.global [%0], [%1], 16;" :: "r"(dst), "l"(src));
}
#define CPA_COMMIT() asm volatile("cp.async.commit_group;" ::: "memory")
#define CPA_WAIT(n)  asm volatile("cp.async.wait_group %0;" :: "n"(n) : "memory")

static __device__ __forceinline__ void mma_tf32(float& d0, float& d1, float& d2, float& d3,
                                                unsigned a0, unsigned a1, unsigned a2, unsigned a3,
                                                unsigned b0, unsigned b1) {
    asm volatile(
        "mma.sync.aligned.m16n8k8.row.col.f32.tf32.tf32.f32 "
        "{%0,%1,%2,%3}, {%4,%5,%6,%7}, {%8,%9}, {%0,%1,%2,%3};"
        : "+f"(d0), "+f"(d1), "+f"(d2), "+f"(d3)
        : "r"(a0), "r"(a1), "r"(a2), "r"(a3), "r"(b0), "r"(b1));
}

// ---------------------------------------------------------------------------
// Prep: L2-normalize q (x10) / k, round everything (incl. v) to tf32.
// One warp per 64-elem row.
// ---------------------------------------------------------------------------
__global__ void __launch_bounds__(256)
prep_kernel(const float* __restrict__ q, const float* __restrict__ k,
            const float* __restrict__ v) {
    const int warp = threadIdx.x >> 5;
    const int lane = threadIdx.x & 31;
    const long long id = (long long)blockIdx.x * 8 + warp;
    const long long nrows = (long long)BH * SS;
    const int seg = (int)(id / nrows);                    // 0=q, 1=k, 2=v
    const int row = (int)(id - (long long)seg * nrows);

    const float* src = (seg == 0) ? q : (seg == 1 ? k : v);
    const float2 v2 = ((const float2*)(src + (size_t)row * DD))[lane];

    if (seg == 2) {
        ((uint2*)(g_vr + (size_t)row * DD))[lane] = make_uint2(tf32r(v2.x), tf32r(v2.y));
        return;
    }
    float ss = v2.x * v2.x + v2.y * v2.y;
    #pragma unroll
    for (int o = 16; o; o >>= 1) ss += __shfl_xor_sync(0xffffffffu, ss, o);
    float scale = 1.0f / fmaxf(sqrtf(ss), 1e-12f);
    if (seg == 0) scale *= 10.0f;

    if (seg == 0) {
        ((uint2*)(g_qn + (size_t)row * DD))[lane] =
            make_uint2(tf32r(v2.x * scale), tf32r(v2.y * scale));
    } else {
        const int bh = row >> 11;
        const int s  = row & (SS - 1);
        unsigned* base = g_kn + (size_t)bh * DD * SS + s;
        base[(size_t)(2 * lane) * SS]     = tf32r(v2.x * scale);
        base[(size_t)(2 * lane + 1) * SS] = tf32r(v2.y * scale);
    }
}

// ---------------------------------------------------------------------------
// Attention: one CTA = 16 q rows of one (b,h).
// ---------------------------------------------------------------------------
__global__ void __launch_bounds__(NT, 1)
attn_kernel(float* __restrict__ outp, float* __restrict__ score) {
    extern __shared__ float sm[];
    float* logits = sm + OFF_LOG;
    float* qt     = sm + OFF_QT;
    const uint32_t base_u = s2u(sm);
    const uint32_t scr_u  = base_u + OFF_SCR * 4;

    const int t    = threadIdx.x;
    const int lane = t & 31;
    const int warp = t >> 5;
    const int gp   = lane >> 2;   // 0..7
    const int tid4 = lane & 3;    // 0..3

    const int bh = blockIdx.x >> 7;
    const int q0 = (blockIdx.x & 127) * TQ;

    const unsigned* qn = g_qn + (size_t)bh * SS * DD;
    const unsigned* kn = g_kn + (size_t)bh * DD * SS;
    const unsigned* vr = g_vr + (size_t)bh * SS * DD;

    // ---- stage q tile ----
    {
        int qi = t >> 4, d4 = t & 15;
        uint4 x = *(const uint4*)(qn + (size_t)(q0 + qi) * DD + d4 * 4);
        *(uint4*)((unsigned*)qt + qi * QTS + d4 * 4) = x;
    }
    __syncthreads();

    // ---- A fragments: entire 16x64 Q tile in registers ----
    unsigned a[8][4];
    {
        const unsigned* qtu = (const unsigned*)qt;
        #pragma unroll
        for (int ks = 0; ks < 8; ks++) {
            a[ks][0] = qtu[gp * QTS + ks * 8 + tid4];
            a[ks][1] = qtu[(gp + 8) * QTS + ks * 8 + tid4];
            a[ks][2] = qtu[gp * QTS + ks * 8 + tid4 + 4];
            a[ks][3] = qtu[(gp + 8) * QTS + ks * 8 + tid4 + 4];
        }
    }

    // ================= Phase 1: logits=exp(Q@K^T), fused row sums =============
    float ps0 = 0.0f, ps1 = 0.0f;   // partial sums for rows gp, gp+8
    {
        const float* kt = sm + OFF_SCR;
        const unsigned* ktu = (const unsigned*)kt;
        for (int ksb = 0; ksb < SS; ksb += 256) {
            __syncthreads();
            #pragma unroll
            for (int i = 0; i < 16; i++) {
                int fidx = i * NT + t;
                int d = fidx >> 6, c4 = fidx & 63;
                cpa16(scr_u + (uint32_t)(d * KTS + c4 * 4) * 4,
                      kn + (size_t)d * SS + ksb + c4 * 4);
            }
            CPA_COMMIT(); CPA_WAIT(0);
            __syncthreads();

            float acc[4][4];
            #pragma unroll
            for (int i = 0; i < 4; i++)
                #pragma unroll
                for (int j = 0; j < 4; j++) acc[i][j] = 0.0f;

            // interleaved: 4 independent accumulator chains
            #pragma unroll
            for (int ks = 0; ks < 8; ks++) {
                unsigned b[4][2];
                #pragma unroll
                for (int nt2 = 0; nt2 < 4; nt2++) {
                    int n0 = warp * 32 + nt2 * 8;
                    b[nt2][0] = ktu[(ks * 8 + tid4) * KTS + n0 + gp];
                    b[nt2][1] = ktu[(ks * 8 + 4 + tid4) * KTS + n0 + gp];
                }
                #pragma unroll
                for (int nt2 = 0; nt2 < 4; nt2++)
                    mma_tf32(acc[nt2][0], acc[nt2][1], acc[nt2][2], acc[nt2][3],
                             a[ks][0], a[ks][1], a[ks][2], a[ks][3],
                             b[nt2][0], b[nt2][1]);
            }

            #pragma unroll
            for (int nt2 = 0; nt2 < 4; nt2++) {
                int n0 = warp * 32 + nt2 * 8;
                float e0 = __expf(acc[nt2][0]);
                float e1 = __expf(acc[nt2][1]);
                float e2 = __expf(acc[nt2][2]);
                float e3 = __expf(acc[nt2][3]);
                ps0 += e0 + e1;
                ps1 += e2 + e3;
                float* lg = logits + gp * LSTRIDE + ksb + n0 + tid4 * 2;
                *(float2*)lg = make_float2(e0, e1);
                *(float2*)(lg + 8 * LSTRIDE) = make_float2(e2, e3);
            }
        }
    }

    // ---- reduce row sums: quad shfl, then across warps via smem ----
    ps0 += __shfl_xor_sync(0xffffffffu, ps0, 1);
    ps0 += __shfl_xor_sync(0xffffffffu, ps0, 2);
    ps1 += __shfl_xor_sync(0xffffffffu, ps1, 1);
    ps1 += __shfl_xor_sync(0xffffffffu, ps1, 2);
    float* sums = qt;          // 16 floats
    float* part = qt + 16;     // [8][16]
    __syncthreads();           // logits writes + qt(frag source) done everywhere
    if (tid4 == 0) {
        part[warp * 16 + gp]     = ps0;
        part[warp * 16 + 8 + gp] = ps1;
    }
    __syncthreads();
    if (t < 16) {
        float s = 0.0f;
        #pragma unroll
        for (int w = 0; w < 8; w++) s += part[w * 16 + t];
        sums[t] = 1.0f / s;
    }
    __syncthreads();

    // ====== Phase 3: out = exp @ V (cp.async double-buffered) + score writes ==
    float acc2[8][4];
    #pragma unroll
    for (int i = 0; i < 8; i++)
        #pragma unroll
        for (int j = 0; j < 4; j++) acc2[i][j] = 0.0f;

    const uint32_t vs_u[2] = { scr_u, scr_u + 9216u * 4u };
    const float* vsf[2] = { sm + OFF_SCR, sm + OFF_SCR + 9216 };

    // preload chunk 0
    {
        #pragma unroll
        for (int i = 0; i < 8; i++) {
            int idx = i * NT + t;
            int kk = idx >> 4, d4 = idx & 15;
            cpa16(vs_u[0] + (uint32_t)(kk * VTS + d4 * 4) * 4,
                  vr + (size_t)kk * DD + d4 * 4);
        }
        CPA_COMMIT();
    }

    const float invA = sums[warp];       // row = warp
    const float invB = sums[warp + 8];   // row = warp+8

    for (int c = 0; c < 16; c++) {
        if (c < 15) {
            uint32_t nb = vs_u[(c + 1) & 1];
            #pragma unroll
            for (int i = 0; i < 8; i++) {
                int idx = i * NT + t;
                int kk = idx >> 4, d4 = idx & 15;
                cpa16(nb + (uint32_t)(kk * VTS + d4 * 4) * 4,
                      vr + (size_t)((c + 1) * 128 + kk) * DD + d4 * 4);
            }
            CPA_COMMIT();
        }

        // score write for cols [c*128, c*128+128), rows warp & warp+8
        {
            float* ra = logits + warp * LSTRIDE + c * 128 + lane * 4;
            float* rb = logits + (warp + 8) * LSTRIDE + c * 128 + lane * 4;
            float4 xa = *(const float4*)ra;
            float4 xb = *(const float4*)rb;
            xa.x *= invA; xa.y *= invA; xa.z *= invA; xa.w *= invA;
            xb.x *= invB; xb.y *= invB; xb.z *= invB; xb.w *= invB;
            float* sa = score + ((size_t)bh * SS + q0 + warp) * SS + c * 128 + lane * 4;
            float* sb = score + ((size_t)bh * SS + q0 + warp + 8) * SS + c * 128 + lane * 4;
            *(float4*)sa = xa;
            *(float4*)sb = xb;
        }

        if (c < 15) { CPA_WAIT(1); } else { CPA_WAIT(0); }
        __syncthreads();

        const unsigned* vsu = (const unsigned*)vsf[c & 1];
        #pragma unroll
        for (int ks = 0; ks < 2; ks++) {
            int kl  = warp * 16 + ks * 8;     // local k row in chunk
            int kgl = c * 128 + kl;           // logits col
            unsigned a0 = tf32r(logits[gp * LSTRIDE + kgl + tid4]);
            unsigned a1 = tf32r(logits[(gp + 8) * LSTRIDE + kgl + tid4]);
            unsigned a2 = tf32r(logits[gp * LSTRIDE + kgl + tid4 + 4]);
            unsigned a3 = tf32r(logits[(gp + 8) * LSTRIDE + kgl + tid4 + 4]);
            #pragma unroll
            for (int nt2 = 0; nt2 < 8; nt2++) {
                unsigned b0 = vsu[(kl + tid4) * VTS + nt2 * 8 + gp];
                unsigned b1 = vsu[(kl + tid4 + 4) * VTS + nt2 * 8 + gp];
                mma_tf32(acc2[nt2][0], acc2[nt2][1], acc2[nt2][2], acc2[nt2][3],
                         a0, a1, a2, a3, b0, b1);
            }
        }
        __syncthreads();   // compute done before next chunk overwrites other buffer
    }

    // ---- cross-warp reduction (red overlays logits, which is now dead) ----
    float* red = sm + OFF_LOG;   // [8][16*64]
    #pragma unroll
    for (int nt2 = 0; nt2 < 8; nt2++) {
        float* m = red + warp * (TQ * DD) + gp * DD + nt2 * 8 + tid4 * 2;
        *(float2*)m = make_float2(acc2[nt2][0], acc2[nt2][1]);
        *(float2*)(m + 8 * DD) = make_float2(acc2[nt2][2], acc2[nt2][3]);
    }
    __syncthreads();
    {
        float* ob = outp + ((size_t)bh * SS + q0) * DD;
        int qi = t >> 4, d0 = (t & 15) * 4;
        float4 s4 = make_float4(0, 0, 0, 0);
        #pragma unroll
        for (int w = 0; w < 8; w++) {
            float4 x = *(const float4*)(red + w * (TQ * DD) + qi * DD + d0);
            s4.x += x.x; s4.y += x.y; s4.z += x.z; s4.w += x.w;
        }
        float inv = sums[qi];
        s4.x *= inv; s4.y *= inv; s4.z *= inv; s4.w *= inv;
        *(float4*)(ob + qi * DD + d0) = s4;
    }
}

// ---------------------------------------------------------------------------
extern "C" void kernel_launch(void* const* d_in, const int* in_sizes, int n_in,
                              void* d_out, int out_size) {
    const float* q = (const float*)d_in[0];
    const float* k = (const float*)d_in[1];
    const float* v = (const float*)d_in[2];

    float* outp  = (float*)d_out;                 // [B,H,S,D]
    float* score = outp + (size_t)BH * SS * DD;   // [B,H,S,S]

    cudaFuncSetAttribute(attn_kernel,
                         cudaFuncAttributeMaxDynamicSharedMemorySize, SMEM_BYTES);

    prep_kernel<<<(3 * BH * SS) / 8, 256>>>(q, k, v);
    attn_kernel<<<BH * (SS / TQ), NT, SMEM_BYTES>>>(outp, score);
}